// round 8
// baseline (speedup 1.0000x reference)
#include <cuda_runtime.h>
#include <cuda_bf16.h>
#include <cstdint>
#include <cstddef>

// ============================================================================
// BitLinear on GB300, sm_103 baseline-PTX path:
//   bf16 HMMA GEMM on integer codes:  y = (absmax-int8(x)) @ ternary(W)^T + b
// codes exact in bf16; fp32 accum exact (|sum| < 2^24).
// R8: ks-software-pipelined fragments (double-buffered LDSM prefetch);
//     4 dummy launches so ncu capture slot lands on gemm_kernel.
// ============================================================================

static constexpr int D_IN  = 2048;
static constexpr int D_OUT = 2048;
static constexpr int M_TOT = 32768;   // 4 * 8192

// scratch (allocation-free rule: device globals)
__device__ __nv_bfloat16 g_qx[(size_t)M_TOT * D_IN];   // 128 MB activation codes
__device__ __nv_bfloat16 g_wq[(size_t)D_OUT * D_IN];   // 8 MB ternary codes
__device__ float  g_scales[M_TOT];                     // per-row activation scale
__device__ float  g_partial[2048];                     // |W| partial sums
__device__ float  g_alpha;                             // ternary scale

// ---------------------------------------------------------------------------
__device__ __forceinline__ float qclip(float v, float s, float lo, float hi) {
    return fminf(fmaxf(rintf(__fdiv_rn(v, s)), lo), hi);
}

__device__ __forceinline__ uint32_t smem_u32(const void* p) {
    uint32_t a;
    asm("{ .reg .u64 t; cvta.to.shared.u64 t, %1; cvt.u32.u64 %0, t; }"
        : "=r"(a) : "l"(p));
    return a;
}

#define LDSM_X4(r, addr) \
    asm volatile("ldmatrix.sync.aligned.m8n8.x4.shared.b16 {%0,%1,%2,%3}, [%4];" \
        : "=r"((r)[0]), "=r"((r)[1]), "=r"((r)[2]), "=r"((r)[3]) : "r"(addr))

// dummy kernel: shifts ncu capture slot onto gemm_kernel (launch #8)
__global__ void k_nop() {}

// ---------------------------------------------------------------------------
// Kernel 1: per-block |W| partial sums (deterministic fixed-order tree)
// ---------------------------------------------------------------------------
__global__ void k_wpartial(const float* __restrict__ w) {
    __shared__ float sh[256];
    const int t = threadIdx.x;
    const float4* p = reinterpret_cast<const float4*>(w + (size_t)blockIdx.x * 2048);
    float s = 0.0f;
#pragma unroll
    for (int k = 0; k < 2; ++k) {
        float4 v = p[2 * t + k];
        s += fabsf(v.x) + fabsf(v.y) + fabsf(v.z) + fabsf(v.w);
    }
    sh[t] = s; __syncthreads();
    for (int o = 128; o > 0; o >>= 1) {
        if (t < o) sh[t] += sh[t + o];
        __syncthreads();
    }
    if (t == 0) g_partial[blockIdx.x] = sh[0];
}

// Kernel 2: final reduce -> alpha = max(mean|W|, eps)
__global__ void k_alpha() {
    __shared__ float sh[256];
    const int t = threadIdx.x;
    float s = 0.0f;
    for (int i = t; i < 2048; i += 256) s += g_partial[i];
    sh[t] = s; __syncthreads();
    for (int o = 128; o > 0; o >>= 1) {
        if (t < o) sh[t] += sh[t + o];
        __syncthreads();
    }
    if (t == 0) g_alpha = fmaxf(sh[0] * (1.0f / 4194304.0f), 1e-5f);
}

// Kernel 3: ternarize W -> bf16 codes {-1,0,1}
__global__ void k_ternarize(const float* __restrict__ w) {
    const size_t i = ((size_t)blockIdx.x * 256 + threadIdx.x) * 4;
    const float a = g_alpha;
    float4 v = *reinterpret_cast<const float4*>(w + i);
    union { uint2 u; __nv_bfloat16 h[4]; } pk;
    pk.h[0] = __float2bfloat16_rn(qclip(v.x, a, -1.0f, 1.0f));
    pk.h[1] = __float2bfloat16_rn(qclip(v.y, a, -1.0f, 1.0f));
    pk.h[2] = __float2bfloat16_rn(qclip(v.z, a, -1.0f, 1.0f));
    pk.h[3] = __float2bfloat16_rn(qclip(v.w, a, -1.0f, 1.0f));
    *reinterpret_cast<uint2*>(g_wq + i) = pk.u;
}

// Kernel 4: per-row absmax int8 quantization of x -> bf16 integer codes
__global__ void k_quant(const float* __restrict__ x) {
    __shared__ float sh[256];
    const int t = threadIdx.x;
    const size_t row = blockIdx.x;
    const float4* xr = reinterpret_cast<const float4*>(x + row * 2048);
    float4 a = xr[2 * t], b = xr[2 * t + 1];
    float m = fmaxf(fmaxf(fmaxf(fabsf(a.x), fabsf(a.y)), fmaxf(fabsf(a.z), fabsf(a.w))),
                    fmaxf(fmaxf(fabsf(b.x), fabsf(b.y)), fmaxf(fabsf(b.z), fabsf(b.w))));
    sh[t] = m; __syncthreads();
    for (int o = 128; o > 0; o >>= 1) {
        if (t < o) sh[t] = fmaxf(sh[t], sh[t + o]);
        __syncthreads();
    }
    const float scale = __fdiv_rn(fmaxf(sh[0], 1e-5f), 127.0f);
    if (t == 0) g_scales[row] = scale;
    union { uint4 u; __nv_bfloat16 h[8]; } pk;
    pk.h[0] = __float2bfloat16_rn(qclip(a.x, scale, -128.0f, 127.0f));
    pk.h[1] = __float2bfloat16_rn(qclip(a.y, scale, -128.0f, 127.0f));
    pk.h[2] = __float2bfloat16_rn(qclip(a.z, scale, -128.0f, 127.0f));
    pk.h[3] = __float2bfloat16_rn(qclip(a.w, scale, -128.0f, 127.0f));
    pk.h[4] = __float2bfloat16_rn(qclip(b.x, scale, -128.0f, 127.0f));
    pk.h[5] = __float2bfloat16_rn(qclip(b.y, scale, -128.0f, 127.0f));
    pk.h[6] = __float2bfloat16_rn(qclip(b.z, scale, -128.0f, 127.0f));
    pk.h[7] = __float2bfloat16_rn(qclip(b.w, scale, -128.0f, 127.0f));
    *reinterpret_cast<uint4*>(g_qx + row * 2048 + (size_t)t * 8) = pk.u;
}

// ---------------------------------------------------------------------------
// Kernel 5: bf16 HMMA GEMM; BM=128 BN=128 BK=64; 4 warps x (64m x 64n);
//   3-stage cp.async pipeline; ks-pipelined ldmatrix; 2 CTAs/SM.
// ---------------------------------------------------------------------------
static constexpr int BM = 128, BN = 128, BK = 64;       // BK in bf16 elements
static constexpr int STAGES = 3;
static constexpr int NITER = D_IN / BK;                 // 32
static constexpr int BKP = 144;                         // padded row bytes (128 data)
static constexpr int STAGE_BYTES = (BM + BN) * BKP;     // 36864
static constexpr int GEMM_SMEM = STAGES * STAGE_BYTES;  // 110592

__device__ __forceinline__ void mma_bf16(float* c, const uint32_t* a, const uint32_t* b) {
    asm volatile(
        "mma.sync.aligned.m16n8k16.row.col.f32.bf16.bf16.f32 "
        "{%0,%1,%2,%3}, {%4,%5,%6,%7}, {%8,%9}, {%0,%1,%2,%3};"
        : "+f"(c[0]), "+f"(c[1]), "+f"(c[2]), "+f"(c[3])
        : "r"(a[0]), "r"(a[1]), "r"(a[2]), "r"(a[3]), "r"(b[0]), "r"(b[1]));
}

__global__ void __launch_bounds__(128, 2)
gemm_kernel(const float* __restrict__ bias, float* __restrict__ out)
{
    extern __shared__ char smem[];
    const int tid = threadIdx.x;
    const int lane = tid & 31, wid = tid >> 5;
    const int warp_m = wid >> 1;          // 0..1 -> 64 rows each
    const int warp_n = wid & 1;           // 0..1 -> 64 cols each
    const int m0 = blockIdx.y * BM;
    const int n0 = blockIdx.x * BN;

    const __nv_bfloat16* gA = g_qx + (size_t)m0 * D_IN;
    const __nv_bfloat16* gB = g_wq + (size_t)n0 * D_IN;

    // --- stage loader: 2048 x 16B chunks (A: 1024, B: 1024); 16 per thread ---
    auto issue_stage = [&](int sOff, int k0 /*elem*/) {
        char* aS = smem + sOff;
        char* bS = aS + BM * BKP;
        const size_t kb = (size_t)k0 * 2;   // bytes into each row
#pragma unroll
        for (int h = 0; h < 16; ++h) {
            const int idx = tid + h * 128;          // [0,2048)
            if (idx < 1024) {
                const int row = idx >> 3, c = idx & 7;
                uint32_t dst = smem_u32(aS + row * BKP + c * 16);
                const char* src = (const char*)(gA + (size_t)row * D_IN) + kb + c * 16;
                asm volatile("cp.async.cg.shared.global [%0], [%1], 16;"
                             :: "r"(dst), "l"(src));
            } else {
                const int j = idx - 1024;
                const int row = j >> 3, c = j & 7;
                uint32_t dst = smem_u32(bS + row * BKP + c * 16);
                const char* src = (const char*)(gB + (size_t)row * D_IN) + kb + c * 16;
                asm volatile("cp.async.cg.shared.global [%0], [%1], 16;"
                             :: "r"(dst), "l"(src));
            }
        }
    };

    float acc[4][8][4];
#pragma unroll
    for (int i = 0; i < 4; ++i)
#pragma unroll
        for (int j = 0; j < 8; ++j)
#pragma unroll
            for (int k = 0; k < 4; ++k) acc[i][j][k] = 0.0f;

    // --- prologue: 2 stages in flight ---
#pragma unroll
    for (int s = 0; s < STAGES - 1; ++s) {
        issue_stage(s * STAGE_BYTES, s * BK);
        asm volatile("cp.async.commit_group;" ::: "memory");
    }

    // ldmatrix per-lane base addresses
    const uint32_t smemb = smem_u32(smem);
    // A frag (m16k16): lanes 0-15 -> rows, lanes 16-31 -> +16B in k
    const uint32_t aLane = smemb
        + (uint32_t)(warp_m * 64 + (lane & 15)) * BKP + ((lane >> 4) << 4);
    // B frag pair (two n8k16 per LDSM.x4): 16 B-rows per LDSM
    const uint32_t bLane = smemb + BM * BKP
        + (uint32_t)(warp_n * 64 + ((lane >> 4) << 3) + (lane & 7)) * BKP
        + (((lane >> 3) & 1) << 4);

    uint32_t cOff = 0;            // compute-stage byte offset
    int loadIt = STAGES - 1;      // next k-iter to load
    uint32_t lOff = (STAGES - 1) * STAGE_BYTES;

    for (int it = 0; it < NITER; ++it) {
        asm volatile("cp.async.wait_group 1;" ::: "memory");
        __syncthreads();

        if (loadIt < NITER)
            issue_stage(lOff, loadIt * BK);
        asm volatile("cp.async.commit_group;" ::: "memory");  // uniform group count
        ++loadIt;
        lOff += STAGE_BYTES; if (lOff == GEMM_SMEM) lOff = 0;

        // --- ks-software-pipelined fragment loads (double-buffered regs) ---
        uint32_t a[2][4][4], b[2][4][4];
#pragma unroll
        for (int mf = 0; mf < 4; ++mf)
            LDSM_X4(a[0][mf], aLane + cOff + (uint32_t)mf * (16 * BKP));
#pragma unroll
        for (int p = 0; p < 4; ++p)
            LDSM_X4(b[0][p], bLane + cOff + (uint32_t)p * (16 * BKP));

#pragma unroll
        for (int ks = 0; ks < 4; ++ks) {
            const int cur = ks & 1, nxt = cur ^ 1;
            if (ks < 3) {
                const uint32_t kb = (uint32_t)(ks + 1) * 32;
#pragma unroll
                for (int mf = 0; mf < 4; ++mf)
                    LDSM_X4(a[nxt][mf], aLane + cOff + (uint32_t)mf * (16 * BKP) + kb);
#pragma unroll
                for (int p = 0; p < 4; ++p)
                    LDSM_X4(b[nxt][p], bLane + cOff + (uint32_t)p * (16 * BKP) + kb);
            }
#pragma unroll
            for (int mf = 0; mf < 4; ++mf)
#pragma unroll
                for (int p = 0; p < 4; ++p) {
                    mma_bf16(acc[mf][p * 2 + 0], a[cur][mf], &b[cur][p][0]);
                    mma_bf16(acc[mf][p * 2 + 1], a[cur][mf], &b[cur][p][2]);
                }
        }
        cOff += STAGE_BYTES; if (cOff == GEMM_SMEM) cOff = 0;
    }

    // --- epilogue: y = acc * (scale_row * alpha) + bias[col] ---
    const float alpha = g_alpha;
    const int colBase = n0 + warp_n * 64 + (lane & 3) * 2;
#pragma unroll
    for (int mf = 0; mf < 4; ++mf) {
        const int row0 = m0 + warp_m * 64 + mf * 16 + (lane >> 2);
        const float sc0 = g_scales[row0] * alpha;
        const float sc1 = g_scales[row0 + 8] * alpha;
        float* o0 = out + (size_t)row0 * D_OUT;
        float* o1 = o0 + (size_t)8 * D_OUT;
#pragma unroll
        for (int nf = 0; nf < 8; ++nf) {
            const int col = colBase + (nf >> 1) * 16 + (nf & 1) * 8;
            const float bx = bias[col], by = bias[col + 1];
            float2 v0, v1;
            v0.x = acc[mf][nf][0] * sc0 + bx;
            v0.y = acc[mf][nf][1] * sc0 + by;
            v1.x = acc[mf][nf][2] * sc1 + bx;
            v1.y = acc[mf][nf][3] * sc1 + by;
            *reinterpret_cast<float2*>(o0 + col) = v0;
            *reinterpret_cast<float2*>(o1 + col) = v1;
        }
    }
}

// ---------------------------------------------------------------------------
extern "C" void kernel_launch(void* const* d_in, const int* in_sizes, int n_in,
                              void* d_out, int out_size) {
    const float* x    = (const float*)d_in[0];   // [4, 8192, 2048]
    const float* w    = (const float*)d_in[1];   // [2048, 2048]
    const float* bias = (const float*)d_in[2];   // [2048]
    float* out = (float*)d_out;

    cudaFuncSetAttribute(gemm_kernel, cudaFuncAttributeMaxDynamicSharedMemorySize,
                         GEMM_SMEM);

    // 4 no-op launches: makes 9 launches per call so the ncu capture slot
    // (observed at absolute launch index 8, == local slot 3 of 5 previously)
    // lands on gemm_kernel instead of k_quant.
    k_nop<<<1, 32>>>();
    k_nop<<<1, 32>>>();
    k_nop<<<1, 32>>>();
    k_nop<<<1, 32>>>();
    k_wpartial<<<2048, 256>>>(w);
    k_alpha<<<1, 256>>>();
    k_ternarize<<<4096, 256>>>(w);
    k_quant<<<M_TOT, 256>>>(x);
    gemm_kernel<<<dim3(D_OUT / BN, M_TOT / BM), 128, GEMM_SMEM>>>(bias, out);
}

// round 9
// speedup vs baseline: 1.0108x; 1.0108x over previous
#include <cuda_runtime.h>
#include <cuda_bf16.h>
#include <cstdint>
#include <cstddef>

// ============================================================================
// BitLinear on GB300, sm_103 baseline-PTX path:
//   bf16 HMMA GEMM on integer codes:  y = (absmax-int8(x)) @ ternary(W)^T + b
// codes exact in bf16; fp32 accum exact (|sum| < 2^24).
// R9: 4-launch schedule (fused |W|-mean kernel) so ncu capture slot (local
//     launch idx 3) lands on gemm_kernel; k_quant warp-shfl reduction.
// ============================================================================

static constexpr int D_IN  = 2048;
static constexpr int D_OUT = 2048;
static constexpr int M_TOT = 32768;   // 4 * 8192

// scratch (allocation-free rule: device globals)
__device__ __nv_bfloat16 g_qx[(size_t)M_TOT * D_IN];   // 128 MB activation codes
__device__ __nv_bfloat16 g_wq[(size_t)D_OUT * D_IN];   // 8 MB ternary codes
__device__ float  g_scales[M_TOT];                     // per-row activation scale
__device__ float  g_partial[2048];                     // |W| partial sums
__device__ float  g_alpha;                             // ternary scale
__device__ unsigned int g_ctr;                         // last-block counter (self-resetting)

// ---------------------------------------------------------------------------
__device__ __forceinline__ float qclip(float v, float s, float lo, float hi) {
    return fminf(fmaxf(rintf(__fdiv_rn(v, s)), lo), hi);
}

__device__ __forceinline__ uint32_t smem_u32(const void* p) {
    uint32_t a;
    asm("{ .reg .u64 t; cvta.to.shared.u64 t, %1; cvt.u32.u64 %0, t; }"
        : "=r"(a) : "l"(p));
    return a;
}

#define LDSM_X4(r, addr) \
    asm volatile("ldmatrix.sync.aligned.m8n8.x4.shared.b16 {%0,%1,%2,%3}, [%4];" \
        : "=r"((r)[0]), "=r"((r)[1]), "=r"((r)[2]), "=r"((r)[3]) : "r"(addr))

// ---------------------------------------------------------------------------
// Kernel 1 (fused): per-block |W| partial sums + last-block final reduce.
// Deterministic: partials use a fixed tree; the final reduce walks g_partial
// in a fixed order. Counter resets itself so graph replays are identical.
// ---------------------------------------------------------------------------
__global__ void k_walpha(const float* __restrict__ w) {
    __shared__ float sh[256];
    __shared__ bool last;
    const int t = threadIdx.x;
    const float4* p = reinterpret_cast<const float4*>(w + (size_t)blockIdx.x * 2048);
    float s = 0.0f;
#pragma unroll
    for (int k = 0; k < 2; ++k) {
        float4 v = p[2 * t + k];
        s += fabsf(v.x) + fabsf(v.y) + fabsf(v.z) + fabsf(v.w);
    }
    sh[t] = s; __syncthreads();
    for (int o = 128; o > 0; o >>= 1) {
        if (t < o) sh[t] += sh[t + o];
        __syncthreads();
    }
    if (t == 0) {
        g_partial[blockIdx.x] = sh[0];
        __threadfence();
        last = (atomicAdd(&g_ctr, 1u) == 2047u);
    }
    __syncthreads();
    if (last) {
        float f = 0.0f;
        for (int i = t; i < 2048; i += 256) f += g_partial[i];
        sh[t] = f; __syncthreads();
        for (int o = 128; o > 0; o >>= 1) {
            if (t < o) sh[t] += sh[t + o];
            __syncthreads();
        }
        if (t == 0) {
            g_alpha = fmaxf(sh[0] * (1.0f / 4194304.0f), 1e-5f);
            g_ctr = 0u;          // reset for next graph replay
        }
    }
}

// Kernel 2: ternarize W -> bf16 codes {-1,0,1}
__global__ void k_ternarize(const float* __restrict__ w) {
    const size_t i = ((size_t)blockIdx.x * 256 + threadIdx.x) * 4;
    const float a = g_alpha;
    float4 v = *reinterpret_cast<const float4*>(w + i);
    union { uint2 u; __nv_bfloat16 h[4]; } pk;
    pk.h[0] = __float2bfloat16_rn(qclip(v.x, a, -1.0f, 1.0f));
    pk.h[1] = __float2bfloat16_rn(qclip(v.y, a, -1.0f, 1.0f));
    pk.h[2] = __float2bfloat16_rn(qclip(v.z, a, -1.0f, 1.0f));
    pk.h[3] = __float2bfloat16_rn(qclip(v.w, a, -1.0f, 1.0f));
    *reinterpret_cast<uint2*>(g_wq + i) = pk.u;
}

// Kernel 3: per-row absmax int8 quantization of x -> bf16 integer codes
// (warp-shfl max: 2 barriers instead of 8)
__global__ void k_quant(const float* __restrict__ x) {
    __shared__ float shw[8];
    const int t = threadIdx.x;
    const int lane = t & 31, wrp = t >> 5;
    const size_t row = blockIdx.x;
    const float4* xr = reinterpret_cast<const float4*>(x + row * 2048);
    float4 a = xr[2 * t], b = xr[2 * t + 1];
    float m = fmaxf(fmaxf(fmaxf(fabsf(a.x), fabsf(a.y)), fmaxf(fabsf(a.z), fabsf(a.w))),
                    fmaxf(fmaxf(fabsf(b.x), fabsf(b.y)), fmaxf(fabsf(b.z), fabsf(b.w))));
#pragma unroll
    for (int o = 16; o > 0; o >>= 1)
        m = fmaxf(m, __shfl_xor_sync(0xFFFFFFFFu, m, o));
    if (lane == 0) shw[wrp] = m;
    __syncthreads();
    if (wrp == 0) {
        float v = shw[lane & 7];
#pragma unroll
        for (int o = 4; o > 0; o >>= 1)
            v = fmaxf(v, __shfl_xor_sync(0xFFFFFFFFu, v, o));
        if (lane == 0) shw[0] = v;
    }
    __syncthreads();
    const float scale = __fdiv_rn(fmaxf(shw[0], 1e-5f), 127.0f);
    if (t == 0) g_scales[row] = scale;
    union { uint4 u; __nv_bfloat16 h[8]; } pk;
    pk.h[0] = __float2bfloat16_rn(qclip(a.x, scale, -128.0f, 127.0f));
    pk.h[1] = __float2bfloat16_rn(qclip(a.y, scale, -128.0f, 127.0f));
    pk.h[2] = __float2bfloat16_rn(qclip(a.z, scale, -128.0f, 127.0f));
    pk.h[3] = __float2bfloat16_rn(qclip(a.w, scale, -128.0f, 127.0f));
    pk.h[4] = __float2bfloat16_rn(qclip(b.x, scale, -128.0f, 127.0f));
    pk.h[5] = __float2bfloat16_rn(qclip(b.y, scale, -128.0f, 127.0f));
    pk.h[6] = __float2bfloat16_rn(qclip(b.z, scale, -128.0f, 127.0f));
    pk.h[7] = __float2bfloat16_rn(qclip(b.w, scale, -128.0f, 127.0f));
    *reinterpret_cast<uint4*>(g_qx + row * 2048 + (size_t)t * 8) = pk.u;
}

// ---------------------------------------------------------------------------
// Kernel 4: bf16 HMMA GEMM; BM=128 BN=128 BK=64; 4 warps x (64m x 64n);
//   3-stage cp.async pipeline; ldmatrix fragments; 2 CTAs/SM.
// ---------------------------------------------------------------------------
static constexpr int BM = 128, BN = 128, BK = 64;       // BK in bf16 elements
static constexpr int STAGES = 3;
static constexpr int NITER = D_IN / BK;                 // 32
static constexpr int BKP = 144;                         // padded row bytes (128 data)
static constexpr int STAGE_BYTES = (BM + BN) * BKP;     // 36864
static constexpr int GEMM_SMEM = STAGES * STAGE_BYTES;  // 110592

__device__ __forceinline__ void mma_bf16(float* c, const uint32_t* a, const uint32_t* b) {
    asm volatile(
        "mma.sync.aligned.m16n8k16.row.col.f32.bf16.bf16.f32 "
        "{%0,%1,%2,%3}, {%4,%5,%6,%7}, {%8,%9}, {%0,%1,%2,%3};"
        : "+f"(c[0]), "+f"(c[1]), "+f"(c[2]), "+f"(c[3])
        : "r"(a[0]), "r"(a[1]), "r"(a[2]), "r"(a[3]), "r"(b[0]), "r"(b[1]));
}

__global__ void __launch_bounds__(128, 2)
gemm_kernel(const float* __restrict__ bias, float* __restrict__ out)
{
    extern __shared__ char smem[];
    const int tid = threadIdx.x;
    const int lane = tid & 31, wid = tid >> 5;
    const int warp_m = wid >> 1;          // 0..1 -> 64 rows each
    const int warp_n = wid & 1;           // 0..1 -> 64 cols each
    const int m0 = blockIdx.y * BM;
    const int n0 = blockIdx.x * BN;

    const __nv_bfloat16* gA = g_qx + (size_t)m0 * D_IN;
    const __nv_bfloat16* gB = g_wq + (size_t)n0 * D_IN;

    // --- stage loader: 2048 x 16B chunks (A: 1024, B: 1024); 16 per thread ---
    auto issue_stage = [&](int sOff, int k0 /*elem*/) {
        char* aS = smem + sOff;
        char* bS = aS + BM * BKP;
        const size_t kb = (size_t)k0 * 2;   // bytes into each row
#pragma unroll
        for (int h = 0; h < 16; ++h) {
            const int idx = tid + h * 128;          // [0,2048)
            if (idx < 1024) {
                const int row = idx >> 3, c = idx & 7;
                uint32_t dst = smem_u32(aS + row * BKP + c * 16);
                const char* src = (const char*)(gA + (size_t)row * D_IN) + kb + c * 16;
                asm volatile("cp.async.cg.shared.global [%0], [%1], 16;"
                             :: "r"(dst), "l"(src));
            } else {
                const int j = idx - 1024;
                const int row = j >> 3, c = j & 7;
                uint32_t dst = smem_u32(bS + row * BKP + c * 16);
                const char* src = (const char*)(gB + (size_t)row * D_IN) + kb + c * 16;
                asm volatile("cp.async.cg.shared.global [%0], [%1], 16;"
                             :: "r"(dst), "l"(src));
            }
        }
    };

    float acc[4][8][4];
#pragma unroll
    for (int i = 0; i < 4; ++i)
#pragma unroll
        for (int j = 0; j < 8; ++j)
#pragma unroll
            for (int k = 0; k < 4; ++k) acc[i][j][k] = 0.0f;

    // --- prologue: 2 stages in flight ---
#pragma unroll
    for (int s = 0; s < STAGES - 1; ++s) {
        issue_stage(s * STAGE_BYTES, s * BK);
        asm volatile("cp.async.commit_group;" ::: "memory");
    }

    // ldmatrix per-lane base addresses
    const uint32_t smemb = smem_u32(smem);
    const uint32_t aLane = smemb
        + (uint32_t)(warp_m * 64 + (lane & 15)) * BKP + ((lane >> 4) << 4);
    const uint32_t bLane = smemb + BM * BKP
        + (uint32_t)(warp_n * 64 + ((lane >> 4) << 3) + (lane & 7)) * BKP
        + (((lane >> 3) & 1) << 4);

    uint32_t cOff = 0;            // compute-stage byte offset
    int loadIt = STAGES - 1;      // next k-iter to load
    uint32_t lOff = (STAGES - 1) * STAGE_BYTES;

    for (int it = 0; it < NITER; ++it) {
        asm volatile("cp.async.wait_group 1;" ::: "memory");
        __syncthreads();

        if (loadIt < NITER)
            issue_stage(lOff, loadIt * BK);
        asm volatile("cp.async.commit_group;" ::: "memory");  // uniform group count
        ++loadIt;
        lOff += STAGE_BYTES; if (lOff == GEMM_SMEM) lOff = 0;

#pragma unroll
        for (int ks = 0; ks < 4; ++ks) {            // 4 x k16 = BK 64 elems
            const uint32_t kb = ks * 32;            // bytes
            uint32_t a[4][4], b[4][4];
#pragma unroll
            for (int mf = 0; mf < 4; ++mf)
                LDSM_X4(a[mf], aLane + cOff + (uint32_t)mf * (16 * BKP) + kb);
#pragma unroll
            for (int p = 0; p < 4; ++p)
                LDSM_X4(b[p], bLane + cOff + (uint32_t)p * (16 * BKP) + kb);
#pragma unroll
            for (int mf = 0; mf < 4; ++mf)
#pragma unroll
                for (int p = 0; p < 4; ++p) {
                    mma_bf16(acc[mf][p * 2 + 0], a[mf], &b[p][0]);
                    mma_bf16(acc[mf][p * 2 + 1], a[mf], &b[p][2]);
                }
        }
        cOff += STAGE_BYTES; if (cOff == GEMM_SMEM) cOff = 0;
    }

    // --- epilogue: y = acc * (scale_row * alpha) + bias[col] ---
    const float alpha = g_alpha;
    const int colBase = n0 + warp_n * 64 + (lane & 3) * 2;
#pragma unroll
    for (int mf = 0; mf < 4; ++mf) {
        const int row0 = m0 + warp_m * 64 + mf * 16 + (lane >> 2);
        const float sc0 = g_scales[row0] * alpha;
        const float sc1 = g_scales[row0 + 8] * alpha;
        float* o0 = out + (size_t)row0 * D_OUT;
        float* o1 = o0 + (size_t)8 * D_OUT;
#pragma unroll
        for (int nf = 0; nf < 8; ++nf) {
            const int col = colBase + (nf >> 1) * 16 + (nf & 1) * 8;
            const float bx = bias[col], by = bias[col + 1];
            float2 v0, v1;
            v0.x = acc[mf][nf][0] * sc0 + bx;
            v0.y = acc[mf][nf][1] * sc0 + by;
            v1.x = acc[mf][nf][2] * sc1 + bx;
            v1.y = acc[mf][nf][3] * sc1 + by;
            *reinterpret_cast<float2*>(o0 + col) = v0;
            *reinterpret_cast<float2*>(o1 + col) = v1;
        }
    }
}

// ---------------------------------------------------------------------------
extern "C" void kernel_launch(void* const* d_in, const int* in_sizes, int n_in,
                              void* d_out, int out_size) {
    const float* x    = (const float*)d_in[0];   // [4, 8192, 2048]
    const float* w    = (const float*)d_in[1];   // [2048, 2048]
    const float* bias = (const float*)d_in[2];   // [2048]
    float* out = (float*)d_out;

    cudaFuncSetAttribute(gemm_kernel, cudaFuncAttributeMaxDynamicSharedMemorySize,
                         GEMM_SMEM);

    // exactly 4 launches: ncu capture slot (local idx 3) = gemm_kernel
    k_walpha<<<2048, 256>>>(w);
    k_ternarize<<<4096, 256>>>(w);
    k_quant<<<M_TOT, 256>>>(x);
    gemm_kernel<<<dim3(D_OUT / BN, M_TOT / BM), 128, GEMM_SMEM>>>(bias, out);
}